// round 1
// baseline (speedup 1.0000x reference)
#include <cuda_runtime.h>
#include <cuda_bf16.h>
#include <cstdint>

// Problem constants (fixed by the reference setup)
#define BATCH   16
#define DDIM    1024
#define NIMG    256            // H*W
#define MTOK    (BATCH * NIMG) // 4096 tokens
#define KCODES  8192
#define DHEAD   1024           // single codebook, d_head == D

// GEMM tiling
#define BM 128
#define BN 128
#define BK 8

// Scratch (allocation-free rule: __device__ globals)
__device__ unsigned long long g_argmin[MTOK];
__device__ float g_esq[KCODES];

// ---------------------------------------------------------------------------
// init: argmin keys to +inf
// ---------------------------------------------------------------------------
__global__ void init_argmin_kernel() {
    int i = blockIdx.x * blockDim.x + threadIdx.x;
    if (i < MTOK) g_argmin[i] = 0xFFFFFFFFFFFFFFFFULL;
}

// ---------------------------------------------------------------------------
// e_sq[k] = sum_c codebook[k][c]^2   (one warp per code row)
// ---------------------------------------------------------------------------
__global__ void esq_kernel(const float* __restrict__ cb) {
    int gwarp = (blockIdx.x * blockDim.x + threadIdx.x) >> 5;
    int lane = threadIdx.x & 31;
    if (gwarp >= KCODES) return;
    const float4* row = reinterpret_cast<const float4*>(cb + (size_t)gwarp * DHEAD);
    float s = 0.f;
    #pragma unroll
    for (int i = lane; i < DHEAD / 4; i += 32) {
        float4 v = row[i];
        s += v.x * v.x + v.y * v.y + v.z * v.z + v.w * v.w;
    }
    #pragma unroll
    for (int o = 16; o > 0; o >>= 1) s += __shfl_xor_sync(0xFFFFFFFFu, s, o);
    if (lane == 0) g_esq[gwarp] = s;
}

// ---------------------------------------------------------------------------
// Fused SGEMM + argmin.
//   A[m][c] = x[b][c][n]  (m = b*256 + n), token matrix, fp32
//   B[k][c] = codebook row, fp32
//   dist[m][k] = e_sq[k] - 2 * dot(A[m], B[k])   (t_sq dropped: constant in k)
//   atomicMin of packed (ordered(dist)<<32 | k) per token.
// ---------------------------------------------------------------------------
__device__ __forceinline__ unsigned long long pack_key(float d, int k) {
    unsigned u = __float_as_uint(d);
    u = (u & 0x80000000u) ? ~u : (u | 0x80000000u); // monotone map float->uint
    return ((unsigned long long)u << 32) | (unsigned)k;
}

__global__ __launch_bounds__(256, 2)
void gemm_argmin_kernel(const float* __restrict__ x, const float* __restrict__ cb) {
    __shared__ float As[2][BK][BM];
    __shared__ float Bs[2][BK][BN + 4];

    const int tid = threadIdx.x;
    const int tx = tid & 15;          // 16 col-threads
    const int ty = tid >> 4;          // 16 row-threads

    const int m0 = blockIdx.y * BM;   // token tile base (aligned within batch)
    const int k0 = blockIdx.x * BN;   // code tile base

    const int b = m0 / NIMG;
    const int n0 = m0 % NIMG;

    // A load mapping: 128x8 tile, 4 scalar loads/thread, coalesced along n
    const int a_lm = tid & 127;                 // local m (== local n)
    const int a_lc0 = tid >> 7;                 // 0 or 1
    const float* a_base = x + (size_t)b * (DDIM * NIMG) + n0 + a_lm;

    // B load mapping: one float4 per thread (128 rows x 8 cols)
    const int b_lk = tid >> 1;
    const int b_lc = (tid & 1) * 4;
    const float* b_base = cb + (size_t)(k0 + b_lk) * DHEAD + b_lc;

    // ---- preload tile 0 ----
    float pa[4];
    float4 pb;
    {
        #pragma unroll
        for (int i = 0; i < 4; i++)
            pa[i] = a_base[(size_t)(a_lc0 + 2 * i) * NIMG];
        pb = *reinterpret_cast<const float4*>(b_base);
        #pragma unroll
        for (int i = 0; i < 4; i++)
            As[0][a_lc0 + 2 * i][a_lm] = pa[i];
        Bs[0][b_lc + 0][b_lk] = pb.x;
        Bs[0][b_lc + 1][b_lk] = pb.y;
        Bs[0][b_lc + 2][b_lk] = pb.z;
        Bs[0][b_lc + 3][b_lk] = pb.w;
    }
    __syncthreads();

    float acc[8][8];
    #pragma unroll
    for (int i = 0; i < 8; i++)
        #pragma unroll
        for (int j = 0; j < 8; j++) acc[i][j] = 0.f;

    const int KT = DHEAD / BK; // 128
    int buf = 0;

    for (int kt = 0; kt < KT; kt++) {
        // stage next tile's global loads
        if (kt < KT - 1) {
            int c0 = (kt + 1) * BK;
            #pragma unroll
            for (int i = 0; i < 4; i++)
                pa[i] = a_base[(size_t)(c0 + a_lc0 + 2 * i) * NIMG];
            pb = *reinterpret_cast<const float4*>(b_base + c0);
        }

        // compute on current buffer
        #pragma unroll
        for (int kk = 0; kk < BK; kk++) {
            float4 a0 = *reinterpret_cast<const float4*>(&As[buf][kk][ty * 8]);
            float4 a1 = *reinterpret_cast<const float4*>(&As[buf][kk][ty * 8 + 4]);
            float4 b0 = *reinterpret_cast<const float4*>(&Bs[buf][kk][tx * 8]);
            float4 b1 = *reinterpret_cast<const float4*>(&Bs[buf][kk][tx * 8 + 4]);
            float a[8] = {a0.x, a0.y, a0.z, a0.w, a1.x, a1.y, a1.z, a1.w};
            float bb[8] = {b0.x, b0.y, b0.z, b0.w, b1.x, b1.y, b1.z, b1.w};
            #pragma unroll
            for (int i = 0; i < 8; i++)
                #pragma unroll
                for (int j = 0; j < 8; j++)
                    acc[i][j] += a[i] * bb[j];
        }

        if (kt < KT - 1) {
            int nb = buf ^ 1;
            #pragma unroll
            for (int i = 0; i < 4; i++)
                As[nb][a_lc0 + 2 * i][a_lm] = pa[i];
            Bs[nb][b_lc + 0][b_lk] = pb.x;
            Bs[nb][b_lc + 1][b_lk] = pb.y;
            Bs[nb][b_lc + 2][b_lk] = pb.z;
            Bs[nb][b_lc + 3][b_lk] = pb.w;
            __syncthreads();
            buf = nb;
        }
    }

    // ---- epilogue: dist = e_sq - 2*cross, per-row argmin, atomic combine ----
    float es[8];
    #pragma unroll
    for (int j = 0; j < 8; j++) es[j] = g_esq[k0 + tx * 8 + j];

    #pragma unroll
    for (int i = 0; i < 8; i++) {
        float bestd = es[0] - 2.f * acc[i][0];
        int bestk = k0 + tx * 8;
        #pragma unroll
        for (int j = 1; j < 8; j++) {
            float d = es[j] - 2.f * acc[i][j];
            if (d < bestd) { bestd = d; bestk = k0 + tx * 8 + j; }
        }
        unsigned long long key = pack_key(bestd, bestk);
        // reduce across the 16 column-threads (same half-warp)
        #pragma unroll
        for (int o = 8; o > 0; o >>= 1) {
            unsigned long long other = __shfl_xor_sync(0xFFFFFFFFu, key, o);
            if (other < key) key = other;
        }
        if (tx == 0) atomicMin(&g_argmin[m0 + ty * 8 + i], key);
    }
}

// ---------------------------------------------------------------------------
// Gather + transpose: out[b][c][n] = values[idx[b*256+n]][c]
// 32x32 tile in smem so both the values read and the out write are coalesced.
// ---------------------------------------------------------------------------
__global__ void gather_kernel(const float* __restrict__ values, float* __restrict__ out) {
    __shared__ float tile[32][33];
    __shared__ int sidx[32];

    const int n_tile = blockIdx.x;  // 0..7
    const int c_tile = blockIdx.y;  // 0..31
    const int b = blockIdx.z;       // 0..15
    const int tx = threadIdx.x;     // 0..31
    const int ty = threadIdx.y;     // 0..7
    const int tid = ty * 32 + tx;

    if (tid < 32) {
        int m = b * NIMG + n_tile * 32 + tid;
        sidx[tid] = (int)(g_argmin[m] & 0xFFFFFFFFULL);
    }
    __syncthreads();

    const int c0 = c_tile * 32;
    #pragma unroll
    for (int r = 0; r < 4; r++) {
        int j = ty + r * 8; // local token
        tile[j][tx] = values[(size_t)sidx[j] * DHEAD + c0 + tx];
    }
    __syncthreads();

    const int n0 = n_tile * 32;
    #pragma unroll
    for (int r = 0; r < 4; r++) {
        int c = ty + r * 8; // local channel
        out[(size_t)b * (DDIM * NIMG) + (size_t)(c0 + c) * NIMG + n0 + tx] = tile[tx][c];
    }
}

// ---------------------------------------------------------------------------
extern "C" void kernel_launch(void* const* d_in, const int* in_sizes, int n_in,
                              void* d_out, int out_size) {
    const float* x      = (const float*)d_in[0]; // [16,1024,16,16]
    const float* cb     = (const float*)d_in[1]; // [1,8192,1024]
    const float* values = (const float*)d_in[2]; // [1,8192,1024]
    float* out          = (float*)d_out;         // [16,1024,16,16]

    init_argmin_kernel<<<(MTOK + 255) / 256, 256>>>();
    esq_kernel<<<(KCODES * 32) / 256, 256>>>(cb);

    dim3 ggrid(KCODES / BN, MTOK / BM); // (64, 32)
    gemm_argmin_kernel<<<ggrid, 256>>>(x, cb);

    dim3 tgrid(NIMG / 32, DDIM / 32, BATCH); // (8, 32, 16)
    gather_kernel<<<tgrid, dim3(32, 8)>>>(values, out);
}

// round 3
// speedup vs baseline: 2.3916x; 2.3916x over previous
#include <cuda_runtime.h>
#include <cuda_bf16.h>
#include <cstdint>

// ---------------------------------------------------------------------------
// Problem constants
// ---------------------------------------------------------------------------
#define BATCH   16
#define DDIM    1024
#define NIMG    256
#define MTOK    (BATCH * NIMG)   // 4096
#define KCODES  8192
#define NTILES  (KCODES / 128)   // 64 code tiles (one per GEMM block column)

// GEMM tiling
#define TM 128
#define TN 128
#define KC 32                    // bf16 channels per chunk (64B rows)
#define NCHUNK (DDIM / KC)       // 32

// Dynamic smem layout
#define OFF_AH 0
#define OFF_AL 8192
#define OFF_BH 16384
#define OFF_BL 24576
#define STAGE  32768
#define ES_OFF   65536                    // 128 floats
#define TOP1_OFF 66560                    // u64 [128][2]
#define TOP2_OFF 68608                    // u64 [128][2]
#define DYN_SMEM 70656

#define EPS 0.02f

// ---------------------------------------------------------------------------
// Global scratch (allocation-free rule: __device__ globals)
// ---------------------------------------------------------------------------
__device__ __nv_bfloat16 g_Ah[MTOK * DDIM];
__device__ __nv_bfloat16 g_Al[MTOK * DDIM];
__device__ float         g_A32[MTOK * DDIM];
__device__ __nv_bfloat16 g_Bh[KCODES * DDIM];
__device__ __nv_bfloat16 g_Bl[KCODES * DDIM];
__device__ float         g_esq[KCODES];
__device__ unsigned long long g_cand1[MTOK * NTILES];
__device__ unsigned long long g_cand2[MTOK * NTILES];
__device__ int           g_idx[MTOK];

// ---------------------------------------------------------------------------
// Helpers
// ---------------------------------------------------------------------------
__device__ __forceinline__ uint32_t smem_u32(const void* p) {
    uint32_t a;
    asm("{ .reg .u64 t; cvta.to.shared.u64 t, %1; cvt.u32.u64 %0, t; }" : "=r"(a) : "l"(p));
    return a;
}

#define CP_ASYNC16(dst, src) \
    asm volatile("cp.async.cg.shared.global [%0], [%1], 16;\n" :: "r"(dst), "l"(src))
#define CP_COMMIT() asm volatile("cp.async.commit_group;\n" ::: "memory")

#define LDSM4(r0, r1, r2, r3, addr)                                         \
    asm volatile("ldmatrix.sync.aligned.m8n8.x4.shared.b16 {%0,%1,%2,%3}, [%4];" \
                 : "=r"(r0), "=r"(r1), "=r"(r2), "=r"(r3) : "r"(addr))

#define MMA16816(acc, a, b0, b1)                                            \
    asm volatile("mma.sync.aligned.m16n8k16.row.col.f32.bf16.bf16.f32 "     \
                 "{%0,%1,%2,%3}, {%4,%5,%6,%7}, {%8,%9}, {%0,%1,%2,%3};"    \
                 : "+f"((acc)[0]), "+f"((acc)[1]), "+f"((acc)[2]), "+f"((acc)[3]) \
                 : "r"((a)[0]), "r"((a)[1]), "r"((a)[2]), "r"((a)[3]),      \
                   "r"(b0), "r"(b1))

__device__ __forceinline__ unsigned long long pack_key(float d, int k) {
    unsigned u = __float_as_uint(d);
    u = (u & 0x80000000u) ? ~u : (u | 0x80000000u);
    return ((unsigned long long)u << 32) | (unsigned)k;
}
__device__ __forceinline__ float unpack_key_d(unsigned long long key) {
    unsigned u = (unsigned)(key >> 32);
    u = (u & 0x80000000u) ? (u ^ 0x80000000u) : ~u;
    return __uint_as_float(u);
}
__device__ __forceinline__ void upd_top2(unsigned long long& k1, unsigned long long& k2,
                                         unsigned long long key) {
    if (key < k1) { k2 = k1; k1 = key; }
    else if (key < k2) { k2 = key; }
}
__device__ __forceinline__ void merge_top2(unsigned long long& k1, unsigned long long& k2,
                                           unsigned long long o1, unsigned long long o2) {
    if (o1 < k1) { k2 = (k1 < o2) ? k1 : o2; k1 = o1; }
    else if (o1 < k2) { k2 = o1; }
}

// swizzled byte offset within a 128-row x 64-byte tile (16B chunk granularity)
__device__ __forceinline__ uint32_t sw_off(int row, int chunk) {
    return (uint32_t)(row * 64 + ((chunk ^ ((row >> 1) & 3)) << 4));
}

// ---------------------------------------------------------------------------
// Prepass: x [B,D,H,W] -> token-major Ah/Al (bf16 split) + A32 (fp32)
// ---------------------------------------------------------------------------
__global__ void convert_x_kernel(const float* __restrict__ x) {
    __shared__ float tile[32][33];
    const int nt = blockIdx.x, ct = blockIdx.y, b = blockIdx.z;
    const int tx = threadIdx.x, ty = threadIdx.y;
    const float* src = x + (size_t)b * (DDIM * NIMG) + (size_t)(ct * 32) * NIMG + nt * 32;
    #pragma unroll
    for (int r = 0; r < 4; r++) {
        int cl = ty + 8 * r;
        tile[cl][tx] = src[(size_t)cl * NIMG + tx];
    }
    __syncthreads();
    const int m0 = b * NIMG + nt * 32;
    #pragma unroll
    for (int r = 0; r < 4; r++) {
        int ml = ty + 8 * r;
        float v = tile[tx][ml];
        __nv_bfloat16 h = __float2bfloat16(v);
        __nv_bfloat16 l = __float2bfloat16(v - __bfloat162float(h));
        size_t o = (size_t)(m0 + ml) * DDIM + ct * 32 + tx;
        g_Ah[o] = h; g_Al[o] = l; g_A32[o] = v;
    }
}

__global__ void convert_cb_kernel(const float* __restrict__ cb) {
    size_t i = ((size_t)blockIdx.x * blockDim.x + threadIdx.x) * 4;
    if (i >= (size_t)KCODES * DDIM) return;
    float4 v = *reinterpret_cast<const float4*>(cb + i);
    float vv[4] = {v.x, v.y, v.z, v.w};
    #pragma unroll
    for (int j = 0; j < 4; j++) {
        __nv_bfloat16 h = __float2bfloat16(vv[j]);
        g_Bh[i + j] = h;
        g_Bl[i + j] = __float2bfloat16(vv[j] - __bfloat162float(h));
    }
}

__global__ void esq_kernel(const float* __restrict__ cb) {
    int gw = (blockIdx.x * blockDim.x + threadIdx.x) >> 5;
    int lane = threadIdx.x & 31;
    if (gw >= KCODES) return;
    const float4* row = reinterpret_cast<const float4*>(cb + (size_t)gw * DDIM);
    float s = 0.f;
    for (int i = lane; i < DDIM / 4; i += 32) {
        float4 v = row[i];
        s += v.x * v.x + v.y * v.y + v.z * v.z + v.w * v.w;
    }
    #pragma unroll
    for (int o = 16; o > 0; o >>= 1) s += __shfl_xor_sync(0xFFFFFFFFu, s, o);
    if (lane == 0) g_esq[gw] = s;
}

// ---------------------------------------------------------------------------
// Main GEMM (mma.sync bf16, 3-term split) + per-tile top-2 epilogue
// ---------------------------------------------------------------------------
__device__ __forceinline__ void load_chunk(uint32_t st, int m0, int k0, int c0, int tid) {
    const __nv_bfloat16* ah = g_Ah;
    const __nv_bfloat16* al = g_Al;
    const __nv_bfloat16* bh = g_Bh;
    const __nv_bfloat16* bl = g_Bl;
    #pragma unroll
    for (int i = 0; i < 2; i++) {
        int vid = tid + i * 256;           // 0..511
        int r = vid >> 2, v = vid & 3;
        uint32_t off = sw_off(r, v);
        size_t ga = (size_t)(m0 + r) * DDIM + c0 + v * 8;
        size_t gb = (size_t)(k0 + r) * DDIM + c0 + v * 8;
        CP_ASYNC16(st + OFF_AH + off, ah + ga);
        CP_ASYNC16(st + OFF_AL + off, al + ga);
        CP_ASYNC16(st + OFF_BH + off, bh + gb);
        CP_ASYNC16(st + OFF_BL + off, bl + gb);
    }
    CP_COMMIT();
}

__global__ __launch_bounds__(256, 2)
void gemm_argmin_kernel() {
    extern __shared__ char dynsm[];
    const int tid = threadIdx.x;
    const int lane = tid & 31;
    const int wid = tid >> 5;
    const int wr = wid & 3;              // M band (32 rows)
    const int wc = wid >> 2;             // N band (64 cols)
    const int bx = blockIdx.x;           // code tile
    const int m0 = blockIdx.y * TM;
    const int k0 = bx * TN;

    const uint32_t smb = smem_u32(dynsm);
    float* s_es = (float*)(dynsm + ES_OFF);
    unsigned long long* s_top1 = (unsigned long long*)(dynsm + TOP1_OFF);
    unsigned long long* s_top2 = (unsigned long long*)(dynsm + TOP2_OFF);

    if (tid < TN) s_es[tid] = g_esq[k0 + tid];

    // ldmatrix address offsets (within a stage), per (tile, kstep)
    uint32_t offA[2][2], offB[4][2];
    #pragma unroll
    for (int mt = 0; mt < 2; mt++)
        #pragma unroll
        for (int ks = 0; ks < 2; ks++) {
            int row = wr * 32 + mt * 16 + (lane & 15);
            int chunk = 2 * ks + (lane >> 4);
            offA[mt][ks] = sw_off(row, chunk);
        }
    #pragma unroll
    for (int g = 0; g < 4; g++)
        #pragma unroll
        for (int ks = 0; ks < 2; ks++) {
            int row = wc * 64 + g * 16 + (lane & 15);
            int chunk = 2 * ks + (lane >> 4);
            offB[g][ks] = sw_off(row, chunk);
        }

    float acc[2][8][4];
    #pragma unroll
    for (int mt = 0; mt < 2; mt++)
        #pragma unroll
        for (int nt = 0; nt < 8; nt++)
            #pragma unroll
            for (int j = 0; j < 4; j++) acc[mt][nt][j] = 0.f;

    load_chunk(smb, m0, k0, 0, tid);

    for (int i = 0; i < NCHUNK; i++) {
        if (i + 1 < NCHUNK)
            load_chunk(smb + ((i + 1) & 1) * STAGE, m0, k0, (i + 1) * KC, tid);
        if (i + 1 < NCHUNK) { asm volatile("cp.async.wait_group 1;\n" ::: "memory"); }
        else                { asm volatile("cp.async.wait_group 0;\n" ::: "memory"); }
        __syncthreads();

        const uint32_t st = smb + (i & 1) * STAGE;
        #pragma unroll
        for (int ks = 0; ks < 2; ks++) {
            uint32_t ahf[2][4], alf[2][4];
            #pragma unroll
            for (int mt = 0; mt < 2; mt++) {
                LDSM4(ahf[mt][0], ahf[mt][1], ahf[mt][2], ahf[mt][3], st + OFF_AH + offA[mt][ks]);
                LDSM4(alf[mt][0], alf[mt][1], alf[mt][2], alf[mt][3], st + OFF_AL + offA[mt][ks]);
            }
            #pragma unroll
            for (int g = 0; g < 4; g++) {
                uint32_t bhf[4], blf[4];
                LDSM4(bhf[0], bhf[1], bhf[2], bhf[3], st + OFF_BH + offB[g][ks]);
                LDSM4(blf[0], blf[1], blf[2], blf[3], st + OFF_BL + offB[g][ks]);
                #pragma unroll
                for (int mt = 0; mt < 2; mt++) {
                    MMA16816(acc[mt][2 * g],     ahf[mt], bhf[0], bhf[2]);
                    MMA16816(acc[mt][2 * g + 1], ahf[mt], bhf[1], bhf[3]);
                    MMA16816(acc[mt][2 * g],     ahf[mt], blf[0], blf[2]);
                    MMA16816(acc[mt][2 * g + 1], ahf[mt], blf[1], blf[3]);
                    MMA16816(acc[mt][2 * g],     alf[mt], bhf[0], bhf[2]);
                    MMA16816(acc[mt][2 * g + 1], alf[mt], bhf[1], bhf[3]);
                }
            }
        }
        __syncthreads();
    }

    // ---- epilogue: dist = e_sq - 2*cross, per-row top-2 over this 128-code tile
    unsigned long long t1[4], t2[4];   // [mt*2 + rhalf]
    #pragma unroll
    for (int i = 0; i < 4; i++) { t1[i] = ~0ULL; t2[i] = ~0ULL; }

    #pragma unroll
    for (int nt = 0; nt < 8; nt++) {
        int cl = wc * 64 + nt * 8 + (lane & 3) * 2;
        float e0 = s_es[cl], e1 = s_es[cl + 1];
        int kg = k0 + cl;
        #pragma unroll
        for (int mt = 0; mt < 2; mt++) {
            upd_top2(t1[mt * 2], t2[mt * 2], pack_key(e0 - 2.f * acc[mt][nt][0], kg));
            upd_top2(t1[mt * 2], t2[mt * 2], pack_key(e1 - 2.f * acc[mt][nt][1], kg + 1));
            upd_top2(t1[mt * 2 + 1], t2[mt * 2 + 1], pack_key(e0 - 2.f * acc[mt][nt][2], kg));
            upd_top2(t1[mt * 2 + 1], t2[mt * 2 + 1], pack_key(e1 - 2.f * acc[mt][nt][3], kg + 1));
        }
    }
    // reduce across the 4 lanes of each row group
    #pragma unroll
    for (int i = 0; i < 4; i++) {
        #pragma unroll
        for (int off = 1; off <= 2; off <<= 1) {
            unsigned long long o1 = __shfl_xor_sync(0xFFFFFFFFu, t1[i], off);
            unsigned long long o2 = __shfl_xor_sync(0xFFFFFFFFu, t2[i], off);
            merge_top2(t1[i], t2[i], o1, o2);
        }
    }
    if ((lane & 3) == 0) {
        #pragma unroll
        for (int i = 0; i < 4; i++) {
            int mt = i >> 1, rh = i & 1;
            int rl = wr * 32 + mt * 16 + (lane >> 2) + rh * 8;
            s_top1[rl * 2 + wc] = t1[i];
            s_top2[rl * 2 + wc] = t2[i];
        }
    }
    __syncthreads();
    if (tid < TM) {
        unsigned long long k1 = s_top1[tid * 2], k2 = s_top2[tid * 2];
        merge_top2(k1, k2, s_top1[tid * 2 + 1], s_top2[tid * 2 + 1]);
        size_t o = (size_t)(m0 + tid) * NTILES + bx;
        g_cand1[o] = k1;
        g_cand2[o] = k2;
    }
}

// ---------------------------------------------------------------------------
// Rescue: global approx min over 128 stored keys; exact fp32 rescore of all
// candidates within EPS; final argmin with jnp tie semantics (smallest k).
// ---------------------------------------------------------------------------
__global__ __launch_bounds__(256)
void rescore_kernel(const float* __restrict__ cb) {
    const int m = blockIdx.x;
    const int tid = threadIdx.x;
    __shared__ unsigned long long keys[2 * NTILES];
    __shared__ int clist[16];
    __shared__ int ccount;
    __shared__ float red[8];
    __shared__ float s_bestd;
    __shared__ int s_bestk;

    if (tid < NTILES)            keys[tid] = g_cand1[(size_t)m * NTILES + tid];
    else if (tid < 2 * NTILES)   keys[tid] = g_cand2[(size_t)m * NTILES + (tid - NTILES)];
    __syncthreads();

    if (tid == 0) {
        unsigned long long best = keys[0];
        for (int i = 1; i < 2 * NTILES; i++) if (keys[i] < best) best = keys[i];
        float bestd = unpack_key_d(best);
        int cnt = 0;
        for (int i = 0; i < 2 * NTILES && cnt < 16; i++) {
            if (unpack_key_d(keys[i]) <= bestd + EPS)
                clist[cnt++] = (int)(keys[i] & 0xFFFFFFFFULL);
        }
        ccount = cnt;
        s_bestd = 3.4e38f; s_bestk = 0x7FFFFFFF;
    }
    __syncthreads();

    const int cnt = ccount;
    float4 tv = *reinterpret_cast<const float4*>(&g_A32[(size_t)m * DDIM + tid * 4]);

    for (int c = 0; c < cnt; c++) {
        int k = clist[c];
        float4 ev = *reinterpret_cast<const float4*>(&cb[(size_t)k * DDIM + tid * 4]);
        float p = tv.x * ev.x + tv.y * ev.y + tv.z * ev.z + tv.w * ev.w;
        #pragma unroll
        for (int o = 16; o > 0; o >>= 1) p += __shfl_xor_sync(0xFFFFFFFFu, p, o);
        if ((tid & 31) == 0) red[tid >> 5] = p;
        __syncthreads();
        if (tid == 0) {
            float dot = 0.f;
            #pragma unroll
            for (int wv = 0; wv < 8; wv++) dot += red[wv];
            float d = g_esq[k] - 2.f * dot;
            if (d < s_bestd || (d == s_bestd && k < s_bestk)) { s_bestd = d; s_bestk = k; }
        }
        __syncthreads();
    }
    if (tid == 0) g_idx[m] = s_bestk;
}

// ---------------------------------------------------------------------------
// Gather + transpose: out[b][c][n] = values[idx[m]][c]
// ---------------------------------------------------------------------------
__global__ void gather_kernel(const float* __restrict__ values, float* __restrict__ out) {
    __shared__ float tile[32][33];
    __shared__ int sidx[32];
    const int nt = blockIdx.x, ct = blockIdx.y, b = blockIdx.z;
    const int tx = threadIdx.x, ty = threadIdx.y;
    const int tid = ty * 32 + tx;
    if (tid < 32) sidx[tid] = g_idx[b * NIMG + nt * 32 + tid];
    __syncthreads();
    const int c0 = ct * 32;
    #pragma unroll
    for (int r = 0; r < 4; r++) {
        int j = ty + r * 8;
        tile[j][tx] = values[(size_t)sidx[j] * DDIM + c0 + tx];
    }
    __syncthreads();
    const int n0 = nt * 32;
    #pragma unroll
    for (int r = 0; r < 4; r++) {
        int c = ty + r * 8;
        out[(size_t)b * (DDIM * NIMG) + (size_t)(c0 + c) * NIMG + n0 + tx] = tile[tx][c];
    }
}

// ---------------------------------------------------------------------------
extern "C" void kernel_launch(void* const* d_in, const int* in_sizes, int n_in,
                              void* d_out, int out_size) {
    const float* x      = (const float*)d_in[0];
    const float* cb     = (const float*)d_in[1];
    const float* values = (const float*)d_in[2];
    float* out          = (float*)d_out;

    static int attr_set = 0;
    if (!attr_set) {
        cudaFuncSetAttribute(gemm_argmin_kernel,
                             cudaFuncAttributeMaxDynamicSharedMemorySize, DYN_SMEM);
        attr_set = 1;
    }

    convert_x_kernel<<<dim3(NIMG / 32, DDIM / 32, BATCH), dim3(32, 8)>>>(x);
    convert_cb_kernel<<<(KCODES * DDIM / 4 + 255) / 256, 256>>>(cb);
    esq_kernel<<<KCODES / 8, 256>>>(cb);

    gemm_argmin_kernel<<<dim3(KCODES / TN, MTOK / TM), 256, DYN_SMEM>>>();

    rescore_kernel<<<MTOK, 256>>>(cb);

    gather_kernel<<<dim3(NIMG / 32, DDIM / 32, BATCH), dim3(32, 8)>>>(values, out);
}

// round 4
// speedup vs baseline: 3.1999x; 1.3380x over previous
#include <cuda_runtime.h>
#include <cuda_fp16.h>
#include <cstdint>

// ---------------------------------------------------------------------------
// Problem constants
// ---------------------------------------------------------------------------
#define BATCH   16
#define DDIM    1024
#define NIMG    256
#define MTOK    (BATCH * NIMG)   // 4096
#define KCODES  8192
#define NTILES  (KCODES / 128)   // 64 code tiles

// GEMM tiling
#define TM 128
#define TN 128
#define KC 32                    // fp16 channels per chunk (64B rows)
#define NCHUNK (DDIM / KC)       // 32
#define NSTAGE 3

// Dynamic smem layout
#define OFF_AH 0
#define OFF_AL 8192
#define OFF_B  16384
#define STAGE  24576
#define ES_OFF   (NSTAGE * STAGE)            // 73728, 128 floats
#define TOP1_OFF (ES_OFF + 512)              // u64 [128][2]
#define TOP2_OFF (TOP1_OFF + 2048)
#define DYN_SMEM (TOP2_OFF + 2048)           // 78336

#define EPS 0.25f

// ---------------------------------------------------------------------------
// Global scratch (allocation-free rule: __device__ globals)
// ---------------------------------------------------------------------------
__device__ __half  g_Ah[MTOK * DDIM];
__device__ __half  g_Al[MTOK * DDIM];
__device__ float   g_A32[MTOK * DDIM];
__device__ __half  g_B[KCODES * DDIM];
__device__ float   g_esq[KCODES];
__device__ unsigned long long g_cand1[MTOK * NTILES];
__device__ unsigned long long g_cand2[MTOK * NTILES];
__device__ int     g_idx[MTOK];

// ---------------------------------------------------------------------------
// Helpers
// ---------------------------------------------------------------------------
__device__ __forceinline__ uint32_t smem_u32(const void* p) {
    uint32_t a;
    asm("{ .reg .u64 t; cvta.to.shared.u64 t, %1; cvt.u32.u64 %0, t; }" : "=r"(a) : "l"(p));
    return a;
}

#define CP_ASYNC16(dst, src) \
    asm volatile("cp.async.cg.shared.global [%0], [%1], 16;\n" :: "r"(dst), "l"(src))
#define CP_COMMIT() asm volatile("cp.async.commit_group;\n" ::: "memory")

#define LDSM4(r0, r1, r2, r3, addr)                                         \
    asm volatile("ldmatrix.sync.aligned.m8n8.x4.shared.b16 {%0,%1,%2,%3}, [%4];" \
                 : "=r"(r0), "=r"(r1), "=r"(r2), "=r"(r3) : "r"(addr))

#define MMA16816(acc, a, b0, b1)                                            \
    asm volatile("mma.sync.aligned.m16n8k16.row.col.f32.f16.f16.f32 "       \
                 "{%0,%1,%2,%3}, {%4,%5,%6,%7}, {%8,%9}, {%0,%1,%2,%3};"    \
                 : "+f"((acc)[0]), "+f"((acc)[1]), "+f"((acc)[2]), "+f"((acc)[3]) \
                 : "r"((a)[0]), "r"((a)[1]), "r"((a)[2]), "r"((a)[3]),      \
                   "r"(b0), "r"(b1))

__device__ __forceinline__ unsigned long long pack_key(float d, int k) {
    unsigned u = __float_as_uint(d);
    u = (u & 0x80000000u) ? ~u : (u | 0x80000000u);
    return ((unsigned long long)u << 32) | (unsigned)k;
}
__device__ __forceinline__ float unpack_key_d(unsigned long long key) {
    unsigned u = (unsigned)(key >> 32);
    u = (u & 0x80000000u) ? (u ^ 0x80000000u) : ~u;
    return __uint_as_float(u);
}
__device__ __forceinline__ void upd_top2(unsigned long long& k1, unsigned long long& k2,
                                         unsigned long long key) {
    if (key < k1) { k2 = k1; k1 = key; }
    else if (key < k2) { k2 = key; }
}
__device__ __forceinline__ void merge_top2(unsigned long long& k1, unsigned long long& k2,
                                           unsigned long long o1, unsigned long long o2) {
    if (o1 < k1) { k2 = (k1 < o2) ? k1 : o2; k1 = o1; }
    else if (o1 < k2) { k2 = o1; }
}

// swizzled byte offset within a 128-row x 64-byte tile (16B chunk granularity)
__device__ __forceinline__ uint32_t sw_off(int row, int chunk) {
    return (uint32_t)(row * 64 + ((chunk ^ ((row >> 1) & 3)) << 4));
}

// ---------------------------------------------------------------------------
// Prepass: x [B,D,H,W] -> token-major Ah/Al (fp16 split) + A32 (fp32)
// ---------------------------------------------------------------------------
__global__ void convert_x_kernel(const float* __restrict__ x) {
    __shared__ float tile[32][33];
    const int nt = blockIdx.x, ct = blockIdx.y, b = blockIdx.z;
    const int tx = threadIdx.x, ty = threadIdx.y;
    const float* src = x + (size_t)b * (DDIM * NIMG) + (size_t)(ct * 32) * NIMG + nt * 32;
    #pragma unroll
    for (int r = 0; r < 4; r++) {
        int cl = ty + 8 * r;
        tile[cl][tx] = src[(size_t)cl * NIMG + tx];
    }
    __syncthreads();
    const int m0 = b * NIMG + nt * 32;
    #pragma unroll
    for (int r = 0; r < 4; r++) {
        int ml = ty + 8 * r;
        float v = tile[tx][ml];
        __half h = __float2half(v);
        __half l = __float2half(v - __half2float(h));
        size_t o = (size_t)(m0 + ml) * DDIM + ct * 32 + tx;
        g_Ah[o] = h; g_Al[o] = l; g_A32[o] = v;
    }
}

// codebook -> fp16 + e_sq fused (one warp per code row)
__global__ void convert_cb_esq_kernel(const float* __restrict__ cb) {
    int gw = (blockIdx.x * blockDim.x + threadIdx.x) >> 5;
    int lane = threadIdx.x & 31;
    if (gw >= KCODES) return;
    const float4* row = reinterpret_cast<const float4*>(cb + (size_t)gw * DDIM);
    float s = 0.f;
    #pragma unroll
    for (int w = 0; w < DDIM / 128; w++) {
        int i = lane + w * 32;                 // float4 index
        float4 v = row[i];
        s += v.x * v.x + v.y * v.y + v.z * v.z + v.w * v.w;
        __half2 h01 = __floats2half2_rn(v.x, v.y);
        __half2 h23 = __floats2half2_rn(v.z, v.w);
        uint2 pk;
        pk.x = *reinterpret_cast<uint32_t*>(&h01);
        pk.y = *reinterpret_cast<uint32_t*>(&h23);
        *reinterpret_cast<uint2*>(&g_B[(size_t)gw * DDIM + i * 4]) = pk;
    }
    #pragma unroll
    for (int o = 16; o > 0; o >>= 1) s += __shfl_xor_sync(0xFFFFFFFFu, s, o);
    if (lane == 0) g_esq[gw] = s;
}

// ---------------------------------------------------------------------------
// Main GEMM (mma.sync fp16, asymmetric 2-term split) + per-tile top-2 epilogue
// ---------------------------------------------------------------------------
__device__ __forceinline__ void load_chunk(uint32_t st, int m0, int k0, int c0, int tid) {
    const __half* ah = g_Ah;
    const __half* al = g_Al;
    const __half* bb = g_B;
    #pragma unroll
    for (int i = 0; i < 2; i++) {
        int vid = tid + i * 256;           // 0..511 covers 128 rows x 4 chunks
        int r = vid >> 2, v = vid & 3;
        uint32_t off = sw_off(r, v);
        size_t ga = (size_t)(m0 + r) * DDIM + c0 + v * 8;
        size_t gb = (size_t)(k0 + r) * DDIM + c0 + v * 8;
        CP_ASYNC16(st + OFF_AH + off, ah + ga);
        CP_ASYNC16(st + OFF_AL + off, al + ga);
        CP_ASYNC16(st + OFF_B + off, bb + gb);
    }
    CP_COMMIT();
}

__global__ __launch_bounds__(256, 2)
void gemm_argmin_kernel() {
    extern __shared__ char dynsm[];
    const int tid = threadIdx.x;
    const int lane = tid & 31;
    const int wid = tid >> 5;
    const int wr = wid & 3;              // M band (32 rows)
    const int wc = wid >> 2;             // N band (64 cols)
    const int bx = blockIdx.x;           // code tile
    const int m0 = blockIdx.y * TM;
    const int k0 = bx * TN;

    const uint32_t smb = smem_u32(dynsm);
    float* s_es = (float*)(dynsm + ES_OFF);
    unsigned long long* s_top1 = (unsigned long long*)(dynsm + TOP1_OFF);
    unsigned long long* s_top2 = (unsigned long long*)(dynsm + TOP2_OFF);

    if (tid < TN) s_es[tid] = g_esq[k0 + tid];

    // ldmatrix address offsets (within a stage), per (tile, kstep)
    uint32_t offA[2][2], offB[4][2];
    #pragma unroll
    for (int mt = 0; mt < 2; mt++)
        #pragma unroll
        for (int ks = 0; ks < 2; ks++) {
            int row = wr * 32 + mt * 16 + (lane & 15);
            int chunk = 2 * ks + (lane >> 4);
            offA[mt][ks] = sw_off(row, chunk);
        }
    #pragma unroll
    for (int g = 0; g < 4; g++)
        #pragma unroll
        for (int ks = 0; ks < 2; ks++) {
            int row = wc * 64 + g * 16 + (lane & 15);
            int chunk = 2 * ks + (lane >> 4);
            offB[g][ks] = sw_off(row, chunk);
        }

    float acc[2][8][4];
    #pragma unroll
    for (int mt = 0; mt < 2; mt++)
        #pragma unroll
        for (int nt = 0; nt < 8; nt++)
            #pragma unroll
            for (int j = 0; j < 4; j++) acc[mt][nt][j] = 0.f;

    load_chunk(smb + 0 * STAGE, m0, k0, 0, tid);
    load_chunk(smb + 1 * STAGE, m0, k0, KC, tid);
    load_chunk(smb + 2 * STAGE, m0, k0, 2 * KC, tid);

    int sidx = 0;
    for (int i = 0; i < NCHUNK; i++) {
        asm volatile("cp.async.wait_group 2;\n" ::: "memory");
        __syncthreads();

        const uint32_t st = smb + sidx * STAGE;
        #pragma unroll
        for (int ks = 0; ks < 2; ks++) {
            uint32_t ahf[2][4], alf[2][4];
            #pragma unroll
            for (int mt = 0; mt < 2; mt++) {
                LDSM4(ahf[mt][0], ahf[mt][1], ahf[mt][2], ahf[mt][3], st + OFF_AH + offA[mt][ks]);
                LDSM4(alf[mt][0], alf[mt][1], alf[mt][2], alf[mt][3], st + OFF_AL + offA[mt][ks]);
            }
            #pragma unroll
            for (int g = 0; g < 4; g++) {
                uint32_t bf[4];
                LDSM4(bf[0], bf[1], bf[2], bf[3], st + OFF_B + offB[g][ks]);
                #pragma unroll
                for (int mt = 0; mt < 2; mt++) {
                    MMA16816(acc[mt][2 * g],     ahf[mt], bf[0], bf[2]);
                    MMA16816(acc[mt][2 * g + 1], ahf[mt], bf[1], bf[3]);
                    MMA16816(acc[mt][2 * g],     alf[mt], bf[0], bf[2]);
                    MMA16816(acc[mt][2 * g + 1], alf[mt], bf[1], bf[3]);
                }
            }
        }
        __syncthreads();
        if (i + NSTAGE < NCHUNK)
            load_chunk(st, m0, k0, (i + NSTAGE) * KC, tid);
        sidx = (sidx == NSTAGE - 1) ? 0 : sidx + 1;
    }

    // ---- epilogue: dist = e_sq - 2*cross, per-row top-2 over this 128-code tile
    unsigned long long t1[4], t2[4];   // [mt*2 + rhalf]
    #pragma unroll
    for (int i = 0; i < 4; i++) { t1[i] = ~0ULL; t2[i] = ~0ULL; }

    #pragma unroll
    for (int nt = 0; nt < 8; nt++) {
        int cl = wc * 64 + nt * 8 + (lane & 3) * 2;
        float e0 = s_es[cl], e1 = s_es[cl + 1];
        int kg = k0 + cl;
        #pragma unroll
        for (int mt = 0; mt < 2; mt++) {
            upd_top2(t1[mt * 2], t2[mt * 2], pack_key(e0 - 2.f * acc[mt][nt][0], kg));
            upd_top2(t1[mt * 2], t2[mt * 2], pack_key(e1 - 2.f * acc[mt][nt][1], kg + 1));
            upd_top2(t1[mt * 2 + 1], t2[mt * 2 + 1], pack_key(e0 - 2.f * acc[mt][nt][2], kg));
            upd_top2(t1[mt * 2 + 1], t2[mt * 2 + 1], pack_key(e1 - 2.f * acc[mt][nt][3], kg + 1));
        }
    }
    #pragma unroll
    for (int i = 0; i < 4; i++) {
        #pragma unroll
        for (int off = 1; off <= 2; off <<= 1) {
            unsigned long long o1 = __shfl_xor_sync(0xFFFFFFFFu, t1[i], off);
            unsigned long long o2 = __shfl_xor_sync(0xFFFFFFFFu, t2[i], off);
            merge_top2(t1[i], t2[i], o1, o2);
        }
    }
    if ((lane & 3) == 0) {
        #pragma unroll
        for (int i = 0; i < 4; i++) {
            int mt = i >> 1, rh = i & 1;
            int rl = wr * 32 + mt * 16 + (lane >> 2) + rh * 8;
            s_top1[rl * 2 + wc] = t1[i];
            s_top2[rl * 2 + wc] = t2[i];
        }
    }
    __syncthreads();
    if (tid < TM) {
        unsigned long long k1 = s_top1[tid * 2], k2 = s_top2[tid * 2];
        merge_top2(k1, k2, s_top1[tid * 2 + 1], s_top2[tid * 2 + 1]);
        size_t o = (size_t)(m0 + tid) * NTILES + bx;
        g_cand1[o] = k1;
        g_cand2[o] = k2;
    }
}

// ---------------------------------------------------------------------------
// Rescue: approx min over 128 stored keys; exact fp32 rescore within EPS.
// ---------------------------------------------------------------------------
__global__ __launch_bounds__(256)
void rescore_kernel(const float* __restrict__ cb) {
    const int m = blockIdx.x;
    const int tid = threadIdx.x;
    __shared__ unsigned long long keys[2 * NTILES];
    __shared__ int clist[16];
    __shared__ int ccount;
    __shared__ float red[8];
    __shared__ float s_bestd;
    __shared__ int s_bestk;

    if (tid < NTILES)            keys[tid] = g_cand1[(size_t)m * NTILES + tid];
    else if (tid < 2 * NTILES)   keys[tid] = g_cand2[(size_t)m * NTILES + (tid - NTILES)];
    __syncthreads();

    if (tid == 0) {
        unsigned long long best = keys[0];
        for (int i = 1; i < 2 * NTILES; i++) if (keys[i] < best) best = keys[i];
        float bestd = unpack_key_d(best);
        int cnt = 0;
        for (int i = 0; i < 2 * NTILES && cnt < 16; i++) {
            if (unpack_key_d(keys[i]) <= bestd + EPS)
                clist[cnt++] = (int)(keys[i] & 0xFFFFFFFFULL);
        }
        ccount = cnt;
        s_bestd = 3.4e38f; s_bestk = 0x7FFFFFFF;
    }
    __syncthreads();

    const int cnt = ccount;
    float4 tv = *reinterpret_cast<const float4*>(&g_A32[(size_t)m * DDIM + tid * 4]);

    for (int c = 0; c < cnt; c++) {
        int k = clist[c];
        float4 ev = *reinterpret_cast<const float4*>(&cb[(size_t)k * DDIM + tid * 4]);
        float p = tv.x * ev.x + tv.y * ev.y + tv.z * ev.z + tv.w * ev.w;
        #pragma unroll
        for (int o = 16; o > 0; o >>= 1) p += __shfl_xor_sync(0xFFFFFFFFu, p, o);
        if ((tid & 31) == 0) red[tid >> 5] = p;
        __syncthreads();
        if (tid == 0) {
            float dot = 0.f;
            #pragma unroll
            for (int wv = 0; wv < 8; wv++) dot += red[wv];
            float d = g_esq[k] - 2.f * dot;
            if (d < s_bestd || (d == s_bestd && k < s_bestk)) { s_bestd = d; s_bestk = k; }
        }
        __syncthreads();
    }
    if (tid == 0) g_idx[m] = s_bestk;
}

// ---------------------------------------------------------------------------
// Gather + transpose: out[b][c][n] = values[idx[m]][c]
// ---------------------------------------------------------------------------
__global__ void gather_kernel(const float* __restrict__ values, float* __restrict__ out) {
    __shared__ float tile[32][33];
    __shared__ int sidx[32];
    const int nt = blockIdx.x, ct = blockIdx.y, b = blockIdx.z;
    const int tx = threadIdx.x, ty = threadIdx.y;
    const int tid = ty * 32 + tx;
    if (tid < 32) sidx[tid] = g_idx[b * NIMG + nt * 32 + tid];
    __syncthreads();
    const int c0 = ct * 32;
    #pragma unroll
    for (int r = 0; r < 4; r++) {
        int j = ty + r * 8;
        tile[j][tx] = values[(size_t)sidx[j] * DDIM + c0 + tx];
    }
    __syncthreads();
    const int n0 = nt * 32;
    #pragma unroll
    for (int r = 0; r < 4; r++) {
        int c = ty + r * 8;
        out[(size_t)b * (DDIM * NIMG) + (size_t)(c0 + c) * NIMG + n0 + tx] = tile[tx][c];
    }
}

// ---------------------------------------------------------------------------
extern "C" void kernel_launch(void* const* d_in, const int* in_sizes, int n_in,
                              void* d_out, int out_size) {
    const float* x      = (const float*)d_in[0];
    const float* cb     = (const float*)d_in[1];
    const float* values = (const float*)d_in[2];
    float* out          = (float*)d_out;

    static int attr_set = 0;
    if (!attr_set) {
        cudaFuncSetAttribute(gemm_argmin_kernel,
                             cudaFuncAttributeMaxDynamicSharedMemorySize, DYN_SMEM);
        attr_set = 1;
    }

    convert_x_kernel<<<dim3(NIMG / 32, DDIM / 32, BATCH), dim3(32, 8)>>>(x);
    convert_cb_esq_kernel<<<KCODES / 8, 256>>>(cb);

    gemm_argmin_kernel<<<dim3(KCODES / TN, MTOK / TM), 256, DYN_SMEM>>>();

    rescore_kernel<<<MTOK, 256>>>(cb);

    gather_kernel<<<dim3(NIMG / 32, DDIM / 32, BATCH), dim3(32, 8)>>>(values, out);
}

// round 5
// speedup vs baseline: 5.5244x; 1.7264x over previous
#include <cuda_runtime.h>
#include <cuda_fp16.h>
#include <cstdint>

// ---------------------------------------------------------------------------
// Problem constants
// ---------------------------------------------------------------------------
#define BATCH   16
#define DDIM    1024
#define NIMG    256
#define MTOK    (BATCH * NIMG)   // 4096
#define KCODES  8192
#define NTILES  (KCODES / 128)   // 64 code tiles

// GEMM tiling
#define TM 128
#define TN 128
#define KC 32                    // fp16 channels per chunk (64B rows)
#define NCHUNK (DDIM / KC)       // 32
#define NSTAGE 4

// Dynamic smem layout
#define OFF_A  0
#define OFF_B  8192
#define STAGE  16384
#define ES_OFF   (NSTAGE * STAGE)            // 65536, 128 floats
#define TOP1_OFF (ES_OFF + 512)              // u64 [128][2]
#define TOP2_OFF (TOP1_OFF + 2048)
#define DYN_SMEM (TOP2_OFF + 2048)           // 70144

#define EPS 0.25f

// ---------------------------------------------------------------------------
// Global scratch (allocation-free rule: __device__ globals)
// ---------------------------------------------------------------------------
__device__ __half  g_A[MTOK * DDIM];
__device__ float   g_A32[MTOK * DDIM];
__device__ __half  g_B[KCODES * DDIM];
__device__ float   g_esq[KCODES];
__device__ unsigned long long g_cand1[MTOK * NTILES];
__device__ unsigned long long g_cand2[MTOK * NTILES];
__device__ int     g_idx[MTOK];

// ---------------------------------------------------------------------------
// Helpers
// ---------------------------------------------------------------------------
__device__ __forceinline__ uint32_t smem_u32(const void* p) {
    uint32_t a;
    asm("{ .reg .u64 t; cvta.to.shared.u64 t, %1; cvt.u32.u64 %0, t; }" : "=r"(a) : "l"(p));
    return a;
}

#define CP_ASYNC16(dst, src) \
    asm volatile("cp.async.cg.shared.global [%0], [%1], 16;\n" :: "r"(dst), "l"(src))
#define CP_COMMIT() asm volatile("cp.async.commit_group;\n" ::: "memory")

#define LDSM4(r0, r1, r2, r3, addr)                                         \
    asm volatile("ldmatrix.sync.aligned.m8n8.x4.shared.b16 {%0,%1,%2,%3}, [%4];" \
                 : "=r"(r0), "=r"(r1), "=r"(r2), "=r"(r3) : "r"(addr))

#define MMA16816(acc, a, b0, b1)                                            \
    asm volatile("mma.sync.aligned.m16n8k16.row.col.f32.f16.f16.f32 "       \
                 "{%0,%1,%2,%3}, {%4,%5,%6,%7}, {%8,%9}, {%0,%1,%2,%3};"    \
                 : "+f"((acc)[0]), "+f"((acc)[1]), "+f"((acc)[2]), "+f"((acc)[3]) \
                 : "r"((a)[0]), "r"((a)[1]), "r"((a)[2]), "r"((a)[3]),      \
                   "r"(b0), "r"(b1))

__device__ __forceinline__ unsigned long long pack_key(float d, int k) {
    unsigned u = __float_as_uint(d);
    u = (u & 0x80000000u) ? ~u : (u | 0x80000000u);
    return ((unsigned long long)u << 32) | (unsigned)k;
}
__device__ __forceinline__ float unpack_key_d(unsigned long long key) {
    unsigned u = (unsigned)(key >> 32);
    u = (u & 0x80000000u) ? (u ^ 0x80000000u) : ~u;
    return __uint_as_float(u);
}
__device__ __forceinline__ void upd_top2(unsigned long long& k1, unsigned long long& k2,
                                         unsigned long long key) {
    if (key < k1) { k2 = k1; k1 = key; }
    else if (key < k2) { k2 = key; }
}
__device__ __forceinline__ void merge_top2(unsigned long long& k1, unsigned long long& k2,
                                           unsigned long long o1, unsigned long long o2) {
    if (o1 < k1) { k2 = (k1 < o2) ? k1 : o2; k1 = o1; }
    else if (o1 < k2) { k2 = o1; }
}

// swizzled byte offset within a 128-row x 64-byte tile (16B chunk granularity)
__device__ __forceinline__ uint32_t sw_off(int row, int chunk) {
    return (uint32_t)(row * 64 + ((chunk ^ ((row >> 1) & 3)) << 4));
}

// ---------------------------------------------------------------------------
// Prepass: x [B,D,H,W] -> token-major A (fp16) + A32 (fp32)
// ---------------------------------------------------------------------------
__global__ void convert_x_kernel(const float* __restrict__ x) {
    __shared__ float tile[32][33];
    const int nt = blockIdx.x, ct = blockIdx.y, b = blockIdx.z;
    const int tx = threadIdx.x, ty = threadIdx.y;
    const float* src = x + (size_t)b * (DDIM * NIMG) + (size_t)(ct * 32) * NIMG + nt * 32;
    #pragma unroll
    for (int r = 0; r < 4; r++) {
        int cl = ty + 8 * r;
        tile[cl][tx] = src[(size_t)cl * NIMG + tx];
    }
    __syncthreads();
    const int m0 = b * NIMG + nt * 32;
    #pragma unroll
    for (int r = 0; r < 4; r++) {
        int ml = ty + 8 * r;
        float v = tile[tx][ml];
        size_t o = (size_t)(m0 + ml) * DDIM + ct * 32 + tx;
        g_A[o] = __float2half(v);
        g_A32[o] = v;
    }
}

// codebook -> fp16 + e_sq fused (one warp per code row)
__global__ void convert_cb_esq_kernel(const float* __restrict__ cb) {
    int gw = (blockIdx.x * blockDim.x + threadIdx.x) >> 5;
    int lane = threadIdx.x & 31;
    if (gw >= KCODES) return;
    const float4* row = reinterpret_cast<const float4*>(cb + (size_t)gw * DDIM);
    float s = 0.f;
    #pragma unroll
    for (int w = 0; w < DDIM / 128; w++) {
        int i = lane + w * 32;                 // float4 index
        float4 v = row[i];
        s += v.x * v.x + v.y * v.y + v.z * v.z + v.w * v.w;
        __half2 h01 = __floats2half2_rn(v.x, v.y);
        __half2 h23 = __floats2half2_rn(v.z, v.w);
        uint2 pk;
        pk.x = *reinterpret_cast<uint32_t*>(&h01);
        pk.y = *reinterpret_cast<uint32_t*>(&h23);
        *reinterpret_cast<uint2*>(&g_B[(size_t)gw * DDIM + i * 4]) = pk;
    }
    #pragma unroll
    for (int o = 16; o > 0; o >>= 1) s += __shfl_xor_sync(0xFFFFFFFFu, s, o);
    if (lane == 0) g_esq[gw] = s;
}

// ---------------------------------------------------------------------------
// Main GEMM (mma.sync fp16, single-term screening) + per-tile top-2 epilogue
// ---------------------------------------------------------------------------
__device__ __forceinline__ void load_chunk(uint32_t st, int m0, int k0, int c0, int tid) {
    const __half* aa = g_A;
    const __half* bb = g_B;
    #pragma unroll
    for (int i = 0; i < 2; i++) {
        int vid = tid + i * 256;           // 0..511 covers 128 rows x 4 chunks
        int r = vid >> 2, v = vid & 3;
        uint32_t off = sw_off(r, v);
        size_t ga = (size_t)(m0 + r) * DDIM + c0 + v * 8;
        size_t gb = (size_t)(k0 + r) * DDIM + c0 + v * 8;
        CP_ASYNC16(st + OFF_A + off, aa + ga);
        CP_ASYNC16(st + OFF_B + off, bb + gb);
    }
    CP_COMMIT();
}

__global__ __launch_bounds__(256, 2)
void gemm_argmin_kernel() {
    extern __shared__ char dynsm[];
    const int tid = threadIdx.x;
    const int lane = tid & 31;
    const int wid = tid >> 5;
    const int wr = wid & 3;              // M band (32 rows)
    const int wc = wid >> 2;             // N band (64 cols)
    const int bx = blockIdx.x;           // code tile
    const int m0 = blockIdx.y * TM;
    const int k0 = bx * TN;

    const uint32_t smb = smem_u32(dynsm);
    float* s_es = (float*)(dynsm + ES_OFF);
    unsigned long long* s_top1 = (unsigned long long*)(dynsm + TOP1_OFF);
    unsigned long long* s_top2 = (unsigned long long*)(dynsm + TOP2_OFF);

    if (tid < TN) s_es[tid] = g_esq[k0 + tid];

    // ldmatrix address offsets (within a stage), per (tile, kstep)
    uint32_t offA[2][2], offB[4][2];
    #pragma unroll
    for (int mt = 0; mt < 2; mt++)
        #pragma unroll
        for (int ks = 0; ks < 2; ks++) {
            int row = wr * 32 + mt * 16 + (lane & 15);
            int chunk = 2 * ks + (lane >> 4);
            offA[mt][ks] = sw_off(row, chunk);
        }
    #pragma unroll
    for (int g = 0; g < 4; g++)
        #pragma unroll
        for (int ks = 0; ks < 2; ks++) {
            int row = wc * 64 + g * 16 + (lane & 15);
            int chunk = 2 * ks + (lane >> 4);
            offB[g][ks] = sw_off(row, chunk);
        }

    float acc[2][8][4];
    #pragma unroll
    for (int mt = 0; mt < 2; mt++)
        #pragma unroll
        for (int nt = 0; nt < 8; nt++)
            #pragma unroll
            for (int j = 0; j < 4; j++) acc[mt][nt][j] = 0.f;

    #pragma unroll
    for (int s = 0; s < NSTAGE; s++)
        load_chunk(smb + s * STAGE, m0, k0, s * KC, tid);

    int sidx = 0;
    for (int i = 0; i < NCHUNK; i++) {
        asm volatile("cp.async.wait_group %0;\n" :: "n"(NSTAGE - 1) : "memory");
        __syncthreads();

        const uint32_t st = smb + sidx * STAGE;
        #pragma unroll
        for (int ks = 0; ks < 2; ks++) {
            uint32_t af[2][4];
            #pragma unroll
            for (int mt = 0; mt < 2; mt++)
                LDSM4(af[mt][0], af[mt][1], af[mt][2], af[mt][3], st + OFF_A + offA[mt][ks]);
            #pragma unroll
            for (int g = 0; g < 4; g++) {
                uint32_t bf[4];
                LDSM4(bf[0], bf[1], bf[2], bf[3], st + OFF_B + offB[g][ks]);
                #pragma unroll
                for (int mt = 0; mt < 2; mt++) {
                    MMA16816(acc[mt][2 * g],     af[mt], bf[0], bf[2]);
                    MMA16816(acc[mt][2 * g + 1], af[mt], bf[1], bf[3]);
                }
            }
        }
        __syncthreads();
        if (i + NSTAGE < NCHUNK)
            load_chunk(st, m0, k0, (i + NSTAGE) * KC, tid);
        sidx = (sidx == NSTAGE - 1) ? 0 : sidx + 1;
    }

    // ---- epilogue: dist = e_sq - 2*cross, per-row top-2 over this 128-code tile
    unsigned long long t1[4], t2[4];   // [mt*2 + rhalf]
    #pragma unroll
    for (int i = 0; i < 4; i++) { t1[i] = ~0ULL; t2[i] = ~0ULL; }

    #pragma unroll
    for (int nt = 0; nt < 8; nt++) {
        int cl = wc * 64 + nt * 8 + (lane & 3) * 2;
        float e0 = s_es[cl], e1 = s_es[cl + 1];
        int kg = k0 + cl;
        #pragma unroll
        for (int mt = 0; mt < 2; mt++) {
            upd_top2(t1[mt * 2], t2[mt * 2], pack_key(e0 - 2.f * acc[mt][nt][0], kg));
            upd_top2(t1[mt * 2], t2[mt * 2], pack_key(e1 - 2.f * acc[mt][nt][1], kg + 1));
            upd_top2(t1[mt * 2 + 1], t2[mt * 2 + 1], pack_key(e0 - 2.f * acc[mt][nt][2], kg));
            upd_top2(t1[mt * 2 + 1], t2[mt * 2 + 1], pack_key(e1 - 2.f * acc[mt][nt][3], kg + 1));
        }
    }
    #pragma unroll
    for (int i = 0; i < 4; i++) {
        #pragma unroll
        for (int off = 1; off <= 2; off <<= 1) {
            unsigned long long o1 = __shfl_xor_sync(0xFFFFFFFFu, t1[i], off);
            unsigned long long o2 = __shfl_xor_sync(0xFFFFFFFFu, t2[i], off);
            merge_top2(t1[i], t2[i], o1, o2);
        }
    }
    if ((lane & 3) == 0) {
        #pragma unroll
        for (int i = 0; i < 4; i++) {
            int mt = i >> 1, rh = i & 1;
            int rl = wr * 32 + mt * 16 + (lane >> 2) + rh * 8;
            s_top1[rl * 2 + wc] = t1[i];
            s_top2[rl * 2 + wc] = t2[i];
        }
    }
    __syncthreads();
    if (tid < TM) {
        unsigned long long k1 = s_top1[tid * 2], k2 = s_top2[tid * 2];
        merge_top2(k1, k2, s_top1[tid * 2 + 1], s_top2[tid * 2 + 1]);
        size_t o = (size_t)(m0 + tid) * NTILES + bx;
        g_cand1[o] = k1;
        g_cand2[o] = k2;
    }
}

// ---------------------------------------------------------------------------
// Rescue: one warp per token; shfl-min over 128 keys, ballot-enumerated
// candidates within EPS, exact fp32 warp dot per candidate. No __syncthreads.
// ---------------------------------------------------------------------------
__global__ __launch_bounds__(256)
void rescore_kernel(const float* __restrict__ cb) {
    const int warp = threadIdx.x >> 5;
    const int lane = threadIdx.x & 31;
    const int m = blockIdx.x * 8 + warp;

    const unsigned long long* c1 = g_cand1 + (size_t)m * NTILES;
    const unsigned long long* c2 = g_cand2 + (size_t)m * NTILES;
    unsigned long long k[4];
    k[0] = c1[lane]; k[1] = c1[lane + 32];
    k[2] = c2[lane]; k[3] = c2[lane + 32];

    unsigned long long mn = k[0];
    if (k[1] < mn) mn = k[1];
    if (k[2] < mn) mn = k[2];
    if (k[3] < mn) mn = k[3];
    #pragma unroll
    for (int o = 16; o > 0; o >>= 1) {
        unsigned long long t = __shfl_xor_sync(0xFFFFFFFFu, mn, o);
        if (t < mn) mn = t;
    }
    const float thr = unpack_key_d(mn) + EPS;

    float bd = 3.4e38f;
    int bk = 0x7FFFFFFF;
    const float4* a4 = reinterpret_cast<const float4*>(g_A32 + (size_t)m * DDIM);

    #pragma unroll
    for (int s = 0; s < 4; s++) {
        unsigned msk = __ballot_sync(0xFFFFFFFFu, unpack_key_d(k[s]) <= thr);
        while (msk) {
            int src = __ffs(msk) - 1;
            msk &= msk - 1;
            int kk = (int)(__shfl_sync(0xFFFFFFFFu, k[s], src) & 0xFFFFFFFFULL);
            const float4* e4 = reinterpret_cast<const float4*>(cb + (size_t)kk * DDIM);
            float p = 0.f;
            #pragma unroll
            for (int w8 = 0; w8 < 8; w8++) {
                float4 a = a4[lane + w8 * 32];
                float4 e = e4[lane + w8 * 32];
                p += a.x * e.x + a.y * e.y + a.z * e.z + a.w * e.w;
            }
            #pragma unroll
            for (int o = 16; o > 0; o >>= 1) p += __shfl_xor_sync(0xFFFFFFFFu, p, o);
            float d = g_esq[kk] - 2.f * p;
            if (d < bd || (d == bd && kk < bk)) { bd = d; bk = kk; }
        }
    }
    if (lane == 0) g_idx[m] = bk;
}

// ---------------------------------------------------------------------------
// Gather + transpose: out[b][c][n] = values[idx[m]][c]
// ---------------------------------------------------------------------------
__global__ void gather_kernel(const float* __restrict__ values, float* __restrict__ out) {
    __shared__ float tile[32][33];
    __shared__ int sidx[32];
    const int nt = blockIdx.x, ct = blockIdx.y, b = blockIdx.z;
    const int tx = threadIdx.x, ty = threadIdx.y;
    const int tid = ty * 32 + tx;
    if (tid < 32) sidx[tid] = g_idx[b * NIMG + nt * 32 + tid];
    __syncthreads();
    const int c0 = ct * 32;
    #pragma unroll
    for (int r = 0; r < 4; r++) {
        int j = ty + r * 8;
        tile[j][tx] = values[(size_t)sidx[j] * DDIM + c0 + tx];
    }
    __syncthreads();
    const int n0 = nt * 32;
    #pragma unroll
    for (int r = 0; r < 4; r++) {
        int c = ty + r * 8;
        out[(size_t)b * (DDIM * NIMG) + (size_t)(c0 + c) * NIMG + n0 + tx] = tile[tx][c];
    }
}

// ---------------------------------------------------------------------------
extern "C" void kernel_launch(void* const* d_in, const int* in_sizes, int n_in,
                              void* d_out, int out_size) {
    const float* x      = (const float*)d_in[0];
    const float* cb     = (const float*)d_in[1];
    const float* values = (const float*)d_in[2];
    float* out          = (float*)d_out;

    static int attr_set = 0;
    if (!attr_set) {
        cudaFuncSetAttribute(gemm_argmin_kernel,
                             cudaFuncAttributeMaxDynamicSharedMemorySize, DYN_SMEM);
        attr_set = 1;
    }

    convert_x_kernel<<<dim3(NIMG / 32, DDIM / 32, BATCH), dim3(32, 8)>>>(x);
    convert_cb_esq_kernel<<<KCODES / 8, 256>>>(cb);

    gemm_argmin_kernel<<<dim3(KCODES / TN, MTOK / TM), 256, DYN_SMEM>>>();

    rescore_kernel<<<MTOK / 8, 256>>>(cb);

    gather_kernel<<<dim3(NIMG / 32, DDIM / 32, BATCH), dim3(32, 8)>>>(values, out);
}